// round 5
// baseline (speedup 1.0000x reference)
#include <cuda_runtime.h>
#include <cuda_bf16.h>
#include <math.h>
#include <stdint.h>

#define NN 50000
#define EE 800000

// ---------------- scratch (no cudaMalloc allowed) ----------------
__device__ float g_tmp[NN * 256];
__device__ float g_v[NN * 64];
__device__ float g_agg[NN * 64];
// CSR structures
__device__ int g_cnt[NN];
__device__ int g_off[NN + 1];
__device__ int g_work[NN];
__device__ int g_ej[EE];
__device__ int g_perm[EE];
__device__ float g_rbf[EE * 12];   // fp32, CSR-sorted
// bf16 hi/lo transposed weights: 10x[256x256] + 8x[64x256 / 256x64]
__device__ __nv_bfloat16 g_wh[10 * 65536 + 8 * 16384];
__device__ __nv_bfloat16 g_wl[10 * 65536 + 8 * 16384];

__device__ __forceinline__ uint32_t smem_u32(const void* p) {
    uint32_t a;
    asm("{ .reg .u64 t; cvta.to.shared.u64 t, %1; cvt.u32.u64 %0, t; }" : "=r"(a) : "l"(p));
    return a;
}

__device__ __forceinline__ void ldsm4(uint32_t& r0, uint32_t& r1, uint32_t& r2,
                                      uint32_t& r3, uint32_t addr) {
    asm volatile("ldmatrix.sync.aligned.m8n8.x4.shared.b16 {%0,%1,%2,%3}, [%4];"
                 : "=r"(r0), "=r"(r1), "=r"(r2), "=r"(r3) : "r"(addr));
}

__device__ __forceinline__ void mma_bf16(float* c, const uint32_t* a, const uint32_t* b) {
    asm volatile(
        "mma.sync.aligned.m16n8k16.row.col.f32.bf16.bf16.f32 "
        "{%0,%1,%2,%3}, {%4,%5,%6,%7}, {%8,%9}, {%0,%1,%2,%3};"
        : "+f"(c[0]), "+f"(c[1]), "+f"(c[2]), "+f"(c[3])
        : "r"(a[0]), "r"(a[1]), "r"(a[2]), "r"(a[3]), "r"(b[0]), "r"(b[1]));
}

__device__ __forceinline__ float gelu_f(float x) {
    float x3 = x * x * x;
    float t = tanhf(0.7978845608028654f * (x + 0.044715f * x3));
    return 0.5f * x * (1.0f + t);
}

// ---------------------------------------------------------------------------
// Weight convert: W [nm][K x N] fp32 -> out [nm][N x K] bf16 hi/lo (transposed)
// ---------------------------------------------------------------------------
__global__ void conv_w_kernel(const float* __restrict__ W,
                              __nv_bfloat16* __restrict__ oh,
                              __nv_bfloat16* __restrict__ ol,
                              int K, int Ncols, int total) {
    int idx = blockIdx.x * blockDim.x + threadIdx.x;
    if (idx >= total) return;
    int kn = K * Ncols;
    int m = idx / kn;
    int r = idx - m * kn;
    int n = r / K;
    int k = r - n * K;
    float w = W[(size_t)m * kn + (size_t)k * Ncols + n];
    __nv_bfloat16 h = __float2bfloat16(w);
    oh[idx] = h;
    ol[idx] = __float2bfloat16(w - __bfloat162float(h));
}

// ---------------------------------------------------------------------------
// HMMA GEMM, template BN in {64,128}. BM=128, BK=32.
// BN=128: 512 threads, 16 warps (4m x 4n), warp tile 32x32.
// BN=64 : 256 threads,  8 warps (4m x 2n), warp tile 32x32.
// 3-product bf16 split: Ah*Bh + Ah*Bl + Al*Bh, fp32 accumulate.
// ---------------------------------------------------------------------------
template <int BN, bool BIAS, bool GELU, bool RESID>
__global__ void __launch_bounds__(BN * 4) mma_gemm(
    const float* __restrict__ A,
    const __nv_bfloat16* __restrict__ Bh_g,
    const __nv_bfloat16* __restrict__ Bl_g,
    const float* __restrict__ bias,
    float* __restrict__ C,
    int rows, int K, int ncols)
{
    constexpr int BM = 128, BK = 32, LD = 40;
    constexpr int NTHR = BN * 4;  // 512 or 256
    __shared__ __nv_bfloat16 sAh[BM * LD];
    __shared__ __nv_bfloat16 sAl[BM * LD];
    __shared__ __nv_bfloat16 sBh[BN * LD];
    __shared__ __nv_bfloat16 sBl[BN * LD];

    int tid = threadIdx.x;
    int lane = tid & 31;
    int wid = tid >> 5;
    int wm = wid & 3;          // 0..3 -> m offset wm*32
    int wn = wid >> 2;         // n offset wn*32 (0..3 or 0..1)
    int r0 = blockIdx.y * BM;
    int c0 = blockIdx.x * BN;

    float acc[2][4][4];
#pragma unroll
    for (int i = 0; i < 2; i++)
#pragma unroll
        for (int j = 0; j < 4; j++)
#pragma unroll
            for (int k = 0; k < 4; k++) acc[i][j][k] = 0.f;

    uint32_t aH = smem_u32(sAh), aL = smem_u32(sAl);
    uint32_t bH = smem_u32(sBh), bL = smem_u32(sBl);

    int a_r = lane & 15;
    int a_c = (lane >> 4) * 8;
    int b_n = ((lane >> 4) * 8) + (lane & 7);
    int b_k = ((lane >> 3) & 1) * 8;

    int nkc = K / BK;
    for (int kc = 0; kc < nkc; kc++) {
        int k0 = kc * BK;
        // --- stage A [128 x 32] fp32 -> bf16 hi/lo ---
        {
            int c4 = tid & 7;
            int rr = tid >> 3;              // 0..NTHR/8-1
#pragma unroll
            for (int q = 0; q < BM / (NTHR / 8); q++) {
                int row = rr + q * (NTHR / 8);
                int gr = r0 + row;
                float4 a = make_float4(0.f, 0.f, 0.f, 0.f);
                if (gr < rows)
                    a = *reinterpret_cast<const float4*>(A + (size_t)gr * K + k0 + c4 * 4);
                __nv_bfloat16 h0 = __float2bfloat16(a.x);
                __nv_bfloat16 h1 = __float2bfloat16(a.y);
                __nv_bfloat16 h2 = __float2bfloat16(a.z);
                __nv_bfloat16 h3 = __float2bfloat16(a.w);
                __nv_bfloat16 l0 = __float2bfloat16(a.x - __bfloat162float(h0));
                __nv_bfloat16 l1 = __float2bfloat16(a.y - __bfloat162float(h1));
                __nv_bfloat16 l2 = __float2bfloat16(a.z - __bfloat162float(h2));
                __nv_bfloat16 l3 = __float2bfloat16(a.w - __bfloat162float(h3));
                uint2 uh = make_uint2(
                    ((uint32_t)__bfloat16_as_ushort(h1) << 16) | __bfloat16_as_ushort(h0),
                    ((uint32_t)__bfloat16_as_ushort(h3) << 16) | __bfloat16_as_ushort(h2));
                uint2 ul = make_uint2(
                    ((uint32_t)__bfloat16_as_ushort(l1) << 16) | __bfloat16_as_ushort(l0),
                    ((uint32_t)__bfloat16_as_ushort(l3) << 16) | __bfloat16_as_ushort(l2));
                *reinterpret_cast<uint2*>(sAh + row * LD + c4 * 4) = uh;
                *reinterpret_cast<uint2*>(sAl + row * LD + c4 * 4) = ul;
            }
        }
        // --- stage B [BN x 32] bf16 hi/lo (copy) ---
        {
            int rowb = tid >> 2;            // 0..BN-1 (NTHR/4 == BN)
            int c8 = tid & 3;
            size_t g = (size_t)(c0 + rowb) * K + k0 + c8 * 8;
            *reinterpret_cast<uint4*>(sBh + rowb * LD + c8 * 8) =
                *reinterpret_cast<const uint4*>(Bh_g + g);
            *reinterpret_cast<uint4*>(sBl + rowb * LD + c8 * 8) =
                *reinterpret_cast<const uint4*>(Bl_g + g);
        }
        __syncthreads();

#pragma unroll
        for (int kk = 0; kk < 2; kk++) {
            uint32_t ah[2][4], al[2][4], bh[2][4], bl[2][4];
#pragma unroll
            for (int im = 0; im < 2; im++) {
                uint32_t off = (uint32_t)(((wm * 32 + im * 16 + a_r) * LD + kk * 16 + a_c) * 2);
                ldsm4(ah[im][0], ah[im][1], ah[im][2], ah[im][3], aH + off);
                ldsm4(al[im][0], al[im][1], al[im][2], al[im][3], aL + off);
            }
#pragma unroll
            for (int jp = 0; jp < 2; jp++) {
                uint32_t off = (uint32_t)(((wn * 32 + jp * 16 + b_n) * LD + kk * 16 + b_k) * 2);
                ldsm4(bh[jp][0], bh[jp][1], bh[jp][2], bh[jp][3], bH + off);
                ldsm4(bl[jp][0], bl[jp][1], bl[jp][2], bl[jp][3], bL + off);
            }
#pragma unroll
            for (int im = 0; im < 2; im++)
#pragma unroll
                for (int jn = 0; jn < 4; jn++) {
                    const uint32_t* pbh = &bh[jn >> 1][(jn & 1) * 2];
                    const uint32_t* pbl = &bl[jn >> 1][(jn & 1) * 2];
                    mma_bf16(acc[im][jn], ah[im], pbh);
                    mma_bf16(acc[im][jn], ah[im], pbl);
                    mma_bf16(acc[im][jn], al[im], pbh);
                }
        }
        __syncthreads();
    }

    // --- epilogue ---
#pragma unroll
    for (int im = 0; im < 2; im++) {
        int rowa = r0 + wm * 32 + im * 16 + (lane >> 2);
        int rowb2 = rowa + 8;
#pragma unroll
        for (int jn = 0; jn < 4; jn++) {
            int col = c0 + wn * 32 + jn * 8 + (lane & 3) * 2;
            float2 bv = make_float2(0.f, 0.f);
            if (BIAS) bv = *reinterpret_cast<const float2*>(bias + col);
#pragma unroll
            for (int h = 0; h < 2; h++) {
                int row = h ? rowb2 : rowa;
                if (row >= rows) continue;
                float vx = acc[im][jn][h * 2 + 0];
                float vy = acc[im][jn][h * 2 + 1];
                if (BIAS) { vx += bv.x; vy += bv.y; }
                if (GELU) { vx = gelu_f(vx); vy = gelu_f(vy); }
                float* p = C + (size_t)row * ncols + col;
                if (RESID) {
                    float2 old = *reinterpret_cast<const float2*>(p);
                    vx += old.x; vy += old.y;
                }
                *reinterpret_cast<float2*>(p) = make_float2(vx, vy);
            }
        }
    }
}

// ---------------------------------------------------------------------------
// Embedding init
// ---------------------------------------------------------------------------
__global__ void embed_kernel(const int* __restrict__ z,
                             const float* __restrict__ table,
                             const float* __restrict__ W,
                             const float* __restrict__ b,
                             float* __restrict__ x, int N) {
    int n = blockIdx.x;
    if (n >= N) return;
    int d = threadIdx.x;
    int t = z[n];
    float acc = b[d];
#pragma unroll
    for (int h = 0; h < 5; h++) acc += table[t * 5 + h] * W[h * 256 + d];
    x[(size_t)n * 256 + d] = acc;
}

// ---------------------------------------------------------------------------
// CSR build: histogram -> scan -> scatter
// ---------------------------------------------------------------------------
__global__ void hist_kernel(const int* __restrict__ ei, int E) {
    int e = blockIdx.x * blockDim.x + threadIdx.x;
    if (e >= E) return;
    atomicAdd(&g_cnt[ei[e]], 1);
}

__global__ void scan_kernel(int N) {
    __shared__ int ssum[1024];
    int t = threadIdx.x;
    int C = (N + 1023) / 1024;
    int lo = t * C;
    int hi = min(N, lo + C);
    int s = 0;
    for (int k = lo; k < hi; k++) s += g_cnt[k];
    ssum[t] = s;
    __syncthreads();
    for (int d = 1; d < 1024; d <<= 1) {
        int v = (t >= d) ? ssum[t - d] : 0;
        __syncthreads();
        ssum[t] += v;
        __syncthreads();
    }
    int pre = (t == 0) ? 0 : ssum[t - 1];
    for (int k = lo; k < hi; k++) {
        g_off[k] = pre;
        g_work[k] = pre;
        pre += g_cnt[k];
    }
    if (t == 1023) g_off[N] = ssum[1023];
}

__global__ void scatter_kernel(const int* __restrict__ ei, int E) {
    int e = blockIdx.x * blockDim.x + threadIdx.x;
    if (e >= E) return;
    int i = ei[e];
    int pos = atomicAdd(&g_work[i], 1);
    g_ej[pos] = ei[E + e];
    g_perm[pos] = e;
}

// ---------------------------------------------------------------------------
// RBF in CSR-sorted order, fp32
// ---------------------------------------------------------------------------
__global__ void rbf_sorted_kernel(const int* __restrict__ ei,
                                  const float* __restrict__ pos,
                                  const float* __restrict__ freqs,
                                  int E) {
    int p = blockIdx.x * blockDim.x + threadIdx.x;
    if (p >= E) return;
    int e = g_perm[p];
    int i = ei[e];
    int j = ei[E + e];
    float dx = pos[i * 3 + 0] - pos[j * 3 + 0];
    float dy = pos[i * 3 + 1] - pos[j * 3 + 1];
    float dz = pos[i * 3 + 2] - pos[j * 3 + 2];
    float dist = sqrtf(dx * dx + dy * dy + dz * dz + 1e-12f);
    float x = dist * 0.2f;
    float x2 = x * x;
    float x4 = x2 * x2;
    float env = 1.0f / x + (-21.0f) * x4 + 35.0f * x4 * x + (-15.0f) * x4 * x2;
#pragma unroll
    for (int r = 0; r < 12; r++)
        g_rbf[(size_t)p * 12 + r] = env * sinf(freqs[r] * x);
}

// ---------------------------------------------------------------------------
// Gather-based edge aggregation: one warp per destination node, no atomics.
// agg[i,m] = sum_{p in seg(i)} v[ej[p], m] * (rbf[p] . Wrbf[:,m])
// ---------------------------------------------------------------------------
__global__ void edge_gather_kernel(const float* __restrict__ Wrbf, int N) {
    __shared__ float sW[12 * 64];
    for (int t = threadIdx.x; t < 12 * 64; t += blockDim.x) sW[t] = Wrbf[t];
    __syncthreads();

    int warp = blockIdx.x * (blockDim.x >> 5) + (threadIdx.x >> 5);
    if (warp >= N) return;
    int lane = threadIdx.x & 31;

    float a0 = 0.f, a1 = 0.f;
    int p0 = g_off[warp];
    int p1 = g_off[warp + 1];
    for (int p = p0; p < p1; p++) {
        int j = g_ej[p];
        const float4* rp = reinterpret_cast<const float4*>(g_rbf + (size_t)p * 12);
        float4 f0 = __ldg(rp);
        float4 f1 = __ldg(rp + 1);
        float4 f2 = __ldg(rp + 2);
        float r[12] = {f0.x, f0.y, f0.z, f0.w, f1.x, f1.y, f1.z, f1.w,
                       f2.x, f2.y, f2.z, f2.w};
        float gg0 = 0.f, gg1 = 0.f;
#pragma unroll
        for (int rr = 0; rr < 12; rr++) {
            gg0 = fmaf(r[rr], sW[rr * 64 + lane], gg0);
            gg1 = fmaf(r[rr], sW[rr * 64 + 32 + lane], gg1);
        }
        a0 = fmaf(__ldg(g_v + (size_t)j * 64 + lane), gg0, a0);
        a1 = fmaf(__ldg(g_v + (size_t)j * 64 + 32 + lane), gg1, a1);
    }
    g_agg[(size_t)warp * 64 + lane] = a0;
    g_agg[(size_t)warp * 64 + 32 + lane] = a1;
}

// ---------------------------------------------------------------------------
// Launcher
// ---------------------------------------------------------------------------
extern "C" void kernel_launch(void* const* d_in, const int* in_sizes, int n_in,
                              void* d_out, int out_size) {
    const int* z = (const int*)d_in[0];
    const float* pos = (const float*)d_in[1];
    const int* ei = (const int*)d_in[4];
    const float* emb_table = (const float*)d_in[5];
    const float* emb_W = (const float*)d_in[6];
    const float* emb_b = (const float*)d_in[7];
    const float* freqs = (const float*)d_in[8];
    const float* fc0_W = (const float*)d_in[9];
    const float* fc0_b = (const float*)d_in[10];
    const float* conv_Wv = (const float*)d_in[11];
    const float* conv_Wrbf = (const float*)d_in[12];
    const float* conv_Wout = (const float*)d_in[13];
    const float* fc_W = (const float*)d_in[14];
    const float* fc_b = (const float*)d_in[15];

    int N = in_sizes[1] / 3;   // 50000
    int E = in_sizes[4] / 2;   // 800000

    float* x = (float*)d_out;

    float *tmp, *vbuf;
    int* cnt;
    __nv_bfloat16 *wh, *wl;
    float* agg;
    cudaGetSymbolAddress((void**)&tmp, g_tmp);
    cudaGetSymbolAddress((void**)&vbuf, g_v);
    cudaGetSymbolAddress((void**)&agg, g_agg);
    cudaGetSymbolAddress((void**)&cnt, g_cnt);
    cudaGetSymbolAddress((void**)&wh, g_wh);
    cudaGetSymbolAddress((void**)&wl, g_wl);

    // ---- weight conversion (hi/lo bf16, transposed) ----
    {
        int T = 2 * 65536;
        conv_w_kernel<<<(T + 255) / 256, 256>>>(fc0_W, wh, wl, 256, 256, T);
        T = 8 * 65536;
        conv_w_kernel<<<(T + 255) / 256, 256>>>(fc_W, wh + 2 * 65536, wl + 2 * 65536, 256, 256, T);
        T = 4 * 16384;
        conv_w_kernel<<<(T + 255) / 256, 256>>>(conv_Wv, wh + 655360, wl + 655360, 256, 64, T);
        conv_w_kernel<<<(T + 255) / 256, 256>>>(conv_Wout, wh + 655360 + 65536,
                                                wl + 655360 + 65536, 64, 256, T);
    }

    // ---- CSR build ----
    cudaMemsetAsync(cnt, 0, N * sizeof(int));
    hist_kernel<<<(E + 255) / 256, 256>>>(ei, E);
    scan_kernel<<<1, 1024>>>(N);
    scatter_kernel<<<(E + 255) / 256, 256>>>(ei, E);
    rbf_sorted_kernel<<<(E + 255) / 256, 256>>>(ei, pos, freqs, E);

    dim3 gridD(2, (N + 127) / 128);   // ncols=256, BN=128
    dim3 gridM(1, (N + 127) / 128);   // ncols=64,  BN=64

    // 1. init embedding
    embed_kernel<<<N, 256>>>(z, emb_table, emb_W, emb_b, x, N);

    // 2. init FC block: x = gelu(gelu(x@W0+b0)@W1+b1)
    mma_gemm<128, true, true, false><<<gridD, 512>>>(x, wh, wl, fc0_b, tmp, N, 256, 256);
    mma_gemm<128, true, true, false><<<gridD, 512>>>(tmp, wh + 65536, wl + 65536,
                                                     fc0_b + 256, x, N, 256, 256);

    // 3. interaction blocks
    for (int n = 0; n < 4; n++) {
        // v = x @ Wv[n]
        mma_gemm<64, false, false, false><<<gridM, 256>>>(
            x, wh + 655360 + n * 16384, wl + 655360 + n * 16384, nullptr,
            vbuf, N, 256, 64);

        // gather-based edge aggregation (8 warps / block)
        edge_gather_kernel<<<(N + 7) / 8, 256>>>(conv_Wrbf + (size_t)n * 12 * 64, N);

        // x = x + agg @ Wout[n]
        mma_gemm<128, false, false, true><<<gridD, 512>>>(
            agg, wh + 655360 + 65536 + n * 16384, wl + 655360 + 65536 + n * 16384,
            nullptr, x, N, 64, 256);

        // x = x + fc_block(x)
        const __nv_bfloat16* W0h = wh + (size_t)(2 + 2 * n) * 65536;
        const __nv_bfloat16* W0l = wl + (size_t)(2 + 2 * n) * 65536;
        const __nv_bfloat16* W1h = wh + (size_t)(3 + 2 * n) * 65536;
        const __nv_bfloat16* W1l = wl + (size_t)(3 + 2 * n) * 65536;
        const float* b0 = fc_b + (size_t)n * 2 * 256;
        const float* b1 = b0 + 256;
        mma_gemm<128, true, true, false><<<gridD, 512>>>(x, W0h, W0l, b0, tmp, N, 256, 256);
        mma_gemm<128, true, true, true><<<gridD, 512>>>(tmp, W1h, W1l, b1, x, N, 256, 256);
    }
}

// round 6
// speedup vs baseline: 1.0748x; 1.0748x over previous
#include <cuda_runtime.h>
#include <cuda_bf16.h>
#include <math.h>
#include <stdint.h>

#define NN 50000
#define EE 800000

// ---------------- scratch (no cudaMalloc allowed) ----------------
__device__ __align__(16) float g_v[NN * 64];
__device__ __align__(16) float g_agg[NN * 64];
__device__ __align__(16) float g_rbf[EE * 12];
// bf16 hi/lo activations
__device__ __align__(16) __nv_bfloat16 g_xh[NN * 256];
__device__ __align__(16) __nv_bfloat16 g_xl[NN * 256];
__device__ __align__(16) __nv_bfloat16 g_th[NN * 256];
__device__ __align__(16) __nv_bfloat16 g_tl[NN * 256];
__device__ __align__(16) __nv_bfloat16 g_aggh[NN * 64];
__device__ __align__(16) __nv_bfloat16 g_aggl[NN * 64];
// bf16 hi/lo transposed weights: 10x[256x256] + 8x[64x256 / 256x64]
__device__ __align__(16) __nv_bfloat16 g_wh[10 * 65536 + 8 * 16384];
__device__ __align__(16) __nv_bfloat16 g_wl[10 * 65536 + 8 * 16384];

__device__ __forceinline__ uint32_t smem_u32(const void* p) {
    uint32_t a;
    asm("{ .reg .u64 t; cvta.to.shared.u64 t, %1; cvt.u32.u64 %0, t; }" : "=r"(a) : "l"(p));
    return a;
}

__device__ __forceinline__ void ldsm4(uint32_t& r0, uint32_t& r1, uint32_t& r2,
                                      uint32_t& r3, uint32_t addr) {
    asm volatile("ldmatrix.sync.aligned.m8n8.x4.shared.b16 {%0,%1,%2,%3}, [%4];"
                 : "=r"(r0), "=r"(r1), "=r"(r2), "=r"(r3) : "r"(addr));
}

__device__ __forceinline__ void mma_bf16(float* c, const uint32_t* a, const uint32_t* b) {
    asm volatile(
        "mma.sync.aligned.m16n8k16.row.col.f32.bf16.bf16.f32 "
        "{%0,%1,%2,%3}, {%4,%5,%6,%7}, {%8,%9}, {%0,%1,%2,%3};"
        : "+f"(c[0]), "+f"(c[1]), "+f"(c[2]), "+f"(c[3])
        : "r"(a[0]), "r"(a[1]), "r"(a[2]), "r"(a[3]), "r"(b[0]), "r"(b[1]));
}

__device__ __forceinline__ void cp16(uint32_t dst, const void* src, int sz) {
    asm volatile("cp.async.cg.shared.global [%0], [%1], 16, %2;"
                 :: "r"(dst), "l"(src), "r"(sz));
}
__device__ __forceinline__ void cp_commit() {
    asm volatile("cp.async.commit_group;" ::: "memory");
}
__device__ __forceinline__ void cp_wait1() {
    asm volatile("cp.async.wait_group 1;" ::: "memory");
}
__device__ __forceinline__ void cp_wait0() {
    asm volatile("cp.async.wait_group 0;" ::: "memory");
}

__device__ __forceinline__ float gelu_f(float x) {
    float x3 = x * x * x;
    float t = tanhf(0.7978845608028654f * (x + 0.044715f * x3));
    return 0.5f * x * (1.0f + t);
}

__device__ __forceinline__ void split_bf16(float v, __nv_bfloat16& h, __nv_bfloat16& l) {
    h = __float2bfloat16(v);
    l = __float2bfloat16(v - __bfloat162float(h));
}

// ---------------------------------------------------------------------------
// Weight convert: W [nm][K x N] fp32 -> out [nm][N x K] bf16 hi/lo (transposed)
// ---------------------------------------------------------------------------
__global__ void conv_w_kernel(const float* __restrict__ W,
                              __nv_bfloat16* __restrict__ oh,
                              __nv_bfloat16* __restrict__ ol,
                              int K, int Ncols, int total) {
    int idx = blockIdx.x * blockDim.x + threadIdx.x;
    if (idx >= total) return;
    int kn = K * Ncols;
    int m = idx / kn;
    int r = idx - m * kn;
    int n = r / K;
    int k = r - n * K;
    float w = W[(size_t)m * kn + (size_t)k * Ncols + n];
    split_bf16(w, oh[idx], ol[idx]);
}

// ---------------------------------------------------------------------------
// HMMA GEMM with pre-split bf16 A, cp.async 2-stage pipeline.
// BM=128, BN=64, BK=32, 256 threads, 8 warps (4m x 2n), warp tile 32x32.
// 3-product split: Ah*Bh + Ah*Bl + Al*Bh, fp32 accumulate.
// Epilogue: bias/gelu/residual; writes fp32 C and/or bf16 hi/lo (Oh/Ol).
// ---------------------------------------------------------------------------
template <bool BIAS, bool GELU, bool RESID, bool OUTF32, bool OUTSPLIT>
__global__ void __launch_bounds__(256) mma_gemm(
    const __nv_bfloat16* __restrict__ Ah_g,
    const __nv_bfloat16* __restrict__ Al_g,
    const __nv_bfloat16* __restrict__ Bh_g,
    const __nv_bfloat16* __restrict__ Bl_g,
    const float* __restrict__ bias,
    float* __restrict__ C,
    __nv_bfloat16* __restrict__ Oh,
    __nv_bfloat16* __restrict__ Ol,
    int rows, int K, int ncols)
{
    constexpr int BM = 128, BN = 64, BK = 32, LD = 40;
    constexpr int ASZ = BM * LD * 2;   // bytes per A component-stage (10240)
    constexpr int BSZ = BN * LD * 2;   // bytes per B component-stage (5120)
    extern __shared__ char smem[];

    int tid = threadIdx.x;
    int lane = tid & 31;
    int wid = tid >> 5;
    int wm = wid & 3;
    int wn = wid >> 2;
    int r0 = blockIdx.y * BM;
    int c0 = blockIdx.x * BN;

    uint32_t sb = smem_u32(smem);
    // layout: AhS0 AhS1 AlS0 AlS1 BhS0 BhS1 BlS0 BlS1
    auto aH = [&](int s) { return sb + (uint32_t)s * ASZ; };
    auto aL = [&](int s) { return sb + 2 * ASZ + (uint32_t)s * ASZ; };
    auto bH = [&](int s) { return sb + 4 * ASZ + (uint32_t)s * BSZ; };
    auto bL = [&](int s) { return sb + 4 * ASZ + 2 * BSZ + (uint32_t)s * BSZ; };

    float acc[2][4][4];
#pragma unroll
    for (int i = 0; i < 2; i++)
#pragma unroll
        for (int j = 0; j < 4; j++)
#pragma unroll
            for (int k = 0; k < 4; k++) acc[i][j][k] = 0.f;

    int a_r = lane & 15;
    int a_c = (lane >> 4) * 8;
    int b_n = ((lane >> 4) * 8) + (lane & 7);
    int b_k = ((lane >> 3) & 1) * 8;

    auto load_stage = [&](int kc, int s) {
        int k0 = kc * BK;
        // A: 128 rows x 2 chunks of 16B per component -> 512 chunks, 2/thread
#pragma unroll
        for (int c = 0; c < 2; c++) {
            int ch = tid + c * 256;
            int row = ch >> 2;
            int c16 = ch & 3;
            int gr = r0 + row;
            int sz = (gr < rows) ? 16 : 0;
            size_t g = (size_t)gr * K + k0 + c16 * 8;
            uint32_t d = (uint32_t)((row * LD + c16 * 8) * 2);
            cp16(aH(s) + d, Ah_g + g, sz);
            cp16(aL(s) + d, Al_g + g, sz);
        }
        // B: 64 rows x 4 chunks -> 256 chunks, 1/thread
        {
            int row = tid >> 2;
            int c16 = tid & 3;
            size_t g = (size_t)(c0 + row) * K + k0 + c16 * 8;
            uint32_t d = (uint32_t)((row * LD + c16 * 8) * 2);
            cp16(bH(s) + d, Bh_g + g, 16);
            cp16(bL(s) + d, Bl_g + g, 16);
        }
    };

    int nkc = K / BK;
    load_stage(0, 0);
    cp_commit();

    for (int kc = 0; kc < nkc; kc++) {
        int s = kc & 1;
        if (kc + 1 < nkc) {
            load_stage(kc + 1, s ^ 1);
            cp_commit();
            cp_wait1();
        } else {
            cp_wait0();
        }
        __syncthreads();

#pragma unroll
        for (int kk = 0; kk < 2; kk++) {
            uint32_t ah[2][4], al[2][4], bh[2][4], bl[2][4];
#pragma unroll
            for (int im = 0; im < 2; im++) {
                uint32_t off = (uint32_t)(((wm * 32 + im * 16 + a_r) * LD + kk * 16 + a_c) * 2);
                ldsm4(ah[im][0], ah[im][1], ah[im][2], ah[im][3], aH(s) + off);
                ldsm4(al[im][0], al[im][1], al[im][2], al[im][3], aL(s) + off);
            }
#pragma unroll
            for (int jp = 0; jp < 2; jp++) {
                uint32_t off = (uint32_t)(((wn * 32 + jp * 16 + b_n) * LD + kk * 16 + b_k) * 2);
                ldsm4(bh[jp][0], bh[jp][1], bh[jp][2], bh[jp][3], bH(s) + off);
                ldsm4(bl[jp][0], bl[jp][1], bl[jp][2], bl[jp][3], bL(s) + off);
            }
#pragma unroll
            for (int im = 0; im < 2; im++)
#pragma unroll
                for (int jn = 0; jn < 4; jn++) {
                    const uint32_t* pbh = &bh[jn >> 1][(jn & 1) * 2];
                    const uint32_t* pbl = &bl[jn >> 1][(jn & 1) * 2];
                    mma_bf16(acc[im][jn], ah[im], pbh);
                    mma_bf16(acc[im][jn], ah[im], pbl);
                    mma_bf16(acc[im][jn], al[im], pbh);
                }
        }
        __syncthreads();
    }

    // --- epilogue ---
#pragma unroll
    for (int im = 0; im < 2; im++) {
        int rowa = r0 + wm * 32 + im * 16 + (lane >> 2);
#pragma unroll
        for (int jn = 0; jn < 4; jn++) {
            int col = c0 + wn * 32 + jn * 8 + (lane & 3) * 2;
            float2 bv = make_float2(0.f, 0.f);
            if (BIAS) bv = *reinterpret_cast<const float2*>(bias + col);
#pragma unroll
            for (int h = 0; h < 2; h++) {
                int row = rowa + h * 8;
                if (row >= rows) continue;
                float vx = acc[im][jn][h * 2 + 0];
                float vy = acc[im][jn][h * 2 + 1];
                if (BIAS) { vx += bv.x; vy += bv.y; }
                if (GELU) { vx = gelu_f(vx); vy = gelu_f(vy); }
                size_t idx = (size_t)row * ncols + col;
                if (RESID) {
                    float2 old = *reinterpret_cast<const float2*>(C + idx);
                    vx += old.x; vy += old.y;
                }
                if (OUTF32)
                    *reinterpret_cast<float2*>(C + idx) = make_float2(vx, vy);
                if (OUTSPLIT) {
                    __nv_bfloat16 hx, lx, hy, ly;
                    split_bf16(vx, hx, lx);
                    split_bf16(vy, hy, ly);
                    *reinterpret_cast<__nv_bfloat162*>(Oh + idx) =
                        __nv_bfloat162(hx, hy);
                    *reinterpret_cast<__nv_bfloat162*>(Ol + idx) =
                        __nv_bfloat162(lx, ly);
                }
            }
        }
    }
}

// ---------------------------------------------------------------------------
// Embedding init -> bf16 hi/lo only
// ---------------------------------------------------------------------------
__global__ void embed_kernel(const int* __restrict__ z,
                             const float* __restrict__ table,
                             const float* __restrict__ W,
                             const float* __restrict__ b, int N) {
    int n = blockIdx.x;
    if (n >= N) return;
    int d = threadIdx.x;
    int t = z[n];
    float acc = b[d];
#pragma unroll
    for (int h = 0; h < 5; h++) acc += table[t * 5 + h] * W[h * 256 + d];
    __nv_bfloat16 hh, ll;
    split_bf16(acc, hh, ll);
    g_xh[(size_t)n * 256 + d] = hh;
    g_xl[(size_t)n * 256 + d] = ll;
}

// ---------------------------------------------------------------------------
// agg fp32 -> bf16 hi/lo
// ---------------------------------------------------------------------------
__global__ void split_agg_kernel(int total) {
    int idx = blockIdx.x * blockDim.x + threadIdx.x;
    if (idx >= total) return;
    split_bf16(g_agg[idx], g_aggh[idx], g_aggl[idx]);
}

// ---------------------------------------------------------------------------
// Bessel RBF with polynomial envelope (p=5)
// ---------------------------------------------------------------------------
__global__ void rbf_kernel(const int* __restrict__ ei,
                           const float* __restrict__ pos,
                           const float* __restrict__ freqs,
                           int E) {
    int e = blockIdx.x * blockDim.x + threadIdx.x;
    if (e >= E) return;
    int i = ei[e];
    int j = ei[E + e];
    float dx = pos[i * 3 + 0] - pos[j * 3 + 0];
    float dy = pos[i * 3 + 1] - pos[j * 3 + 1];
    float dz = pos[i * 3 + 2] - pos[j * 3 + 2];
    float dist = sqrtf(dx * dx + dy * dy + dz * dz + 1e-12f);
    float x = dist * 0.2f;
    float x2 = x * x;
    float x4 = x2 * x2;
    float env = 1.0f / x + (-21.0f) * x4 + 35.0f * x4 * x + (-15.0f) * x4 * x2;
#pragma unroll
    for (int r = 0; r < 12; r++)
        g_rbf[(size_t)e * 12 + r] = env * sinf(freqs[r] * x);
}

// ---------------------------------------------------------------------------
// Edge messages + scatter: 16 threads/edge, vector red.global.add.v4.f32
// ---------------------------------------------------------------------------
__global__ void edge_msg_kernel(const int* __restrict__ ei,
                                const float* __restrict__ Wrbf,  // [12,64]
                                int E) {
    __shared__ float sW[12 * 64];
    for (int t = threadIdx.x; t < 12 * 64; t += blockDim.x) sW[t] = Wrbf[t];
    __syncthreads();

    int gt = blockIdx.x * blockDim.x + threadIdx.x;
    int e = gt >> 4;
    if (e >= E) return;
    int sub = gt & 15;
    int m0 = sub * 4;

    int i = ei[e];
    int j = ei[E + e];

    float gx = 0.f, gy = 0.f, gz = 0.f, gw = 0.f;
#pragma unroll
    for (int r = 0; r < 12; r++) {
        float rv = __ldg(&g_rbf[(size_t)e * 12 + r]);
        const float* w = &sW[r * 64 + m0];
        gx = fmaf(rv, w[0], gx);
        gy = fmaf(rv, w[1], gy);
        gz = fmaf(rv, w[2], gz);
        gw = fmaf(rv, w[3], gw);
    }
    const float4 vj = *reinterpret_cast<const float4*>(g_v + (size_t)j * 64 + m0);
    float vx = vj.x * gx, vy = vj.y * gy, vz = vj.z * gz, vw = vj.w * gw;
    float* dst = g_agg + (size_t)i * 64 + m0;
    asm volatile("red.global.add.v4.f32 [%0], {%1, %2, %3, %4};"
                 :: "l"(dst), "f"(vx), "f"(vy), "f"(vz), "f"(vw) : "memory");
}

// ---------------------------------------------------------------------------
// Launcher
// ---------------------------------------------------------------------------
extern "C" void kernel_launch(void* const* d_in, const int* in_sizes, int n_in,
                              void* d_out, int out_size) {
    const int* z = (const int*)d_in[0];
    const float* pos = (const float*)d_in[1];
    const int* ei = (const int*)d_in[4];
    const float* emb_table = (const float*)d_in[5];
    const float* emb_W = (const float*)d_in[6];
    const float* emb_b = (const float*)d_in[7];
    const float* freqs = (const float*)d_in[8];
    const float* fc0_W = (const float*)d_in[9];
    const float* fc0_b = (const float*)d_in[10];
    const float* conv_Wv = (const float*)d_in[11];
    const float* conv_Wrbf = (const float*)d_in[12];
    const float* conv_Wout = (const float*)d_in[13];
    const float* fc_W = (const float*)d_in[14];
    const float* fc_b = (const float*)d_in[15];

    int N = in_sizes[1] / 3;   // 50000
    int E = in_sizes[4] / 2;   // 800000

    float* x = (float*)d_out;

    float *vbuf, *agg;
    __nv_bfloat16 *wh, *wl, *xh, *xl, *th, *tl, *aggh, *aggl;
    cudaGetSymbolAddress((void**)&vbuf, g_v);
    cudaGetSymbolAddress((void**)&agg, g_agg);
    cudaGetSymbolAddress((void**)&wh, g_wh);
    cudaGetSymbolAddress((void**)&wl, g_wl);
    cudaGetSymbolAddress((void**)&xh, g_xh);
    cudaGetSymbolAddress((void**)&xl, g_xl);
    cudaGetSymbolAddress((void**)&th, g_th);
    cudaGetSymbolAddress((void**)&tl, g_tl);
    cudaGetSymbolAddress((void**)&aggh, g_aggh);
    cudaGetSymbolAddress((void**)&aggl, g_aggl);

    const int SMEM = 4 * (128 * 40 * 2) + 4 * (64 * 40 * 2);  // 61440
    cudaFuncSetAttribute((const void*)mma_gemm<true, true, false, false, true>,
                         cudaFuncAttributeMaxDynamicSharedMemorySize, SMEM);
    cudaFuncSetAttribute((const void*)mma_gemm<true, true, false, true, true>,
                         cudaFuncAttributeMaxDynamicSharedMemorySize, SMEM);
    cudaFuncSetAttribute((const void*)mma_gemm<true, true, true, true, true>,
                         cudaFuncAttributeMaxDynamicSharedMemorySize, SMEM);
    cudaFuncSetAttribute((const void*)mma_gemm<false, false, false, true, false>,
                         cudaFuncAttributeMaxDynamicSharedMemorySize, SMEM);
    cudaFuncSetAttribute((const void*)mma_gemm<false, false, true, true, true>,
                         cudaFuncAttributeMaxDynamicSharedMemorySize, SMEM);

    // ---- weight conversion (hi/lo bf16, transposed) ----
    {
        int T = 2 * 65536;
        conv_w_kernel<<<(T + 255) / 256, 256>>>(fc0_W, wh, wl, 256, 256, T);
        T = 8 * 65536;
        conv_w_kernel<<<(T + 255) / 256, 256>>>(fc_W, wh + 2 * 65536, wl + 2 * 65536, 256, 256, T);
        T = 4 * 16384;
        conv_w_kernel<<<(T + 255) / 256, 256>>>(conv_Wv, wh + 655360, wl + 655360, 256, 64, T);
        conv_w_kernel<<<(T + 255) / 256, 256>>>(conv_Wout, wh + 655360 + 65536,
                                                wl + 655360 + 65536, 64, 256, T);
    }

    dim3 gridD(4, (N + 127) / 128);   // ncols=256
    dim3 gridM(1, (N + 127) / 128);   // ncols=64

    // 1. init embedding (split only)
    embed_kernel<<<N, 256>>>(z, emb_table, emb_W, emb_b, N);

    // 2. init FC block
    // tmp = gelu(x@W0+b0)  (split only)
    mma_gemm<true, true, false, false, true><<<gridD, 256, SMEM>>>(
        xh, xl, wh, wl, fc0_b, nullptr, th, tl, N, 256, 256);
    // x = gelu(tmp@W1+b1)  (fp32 + split)
    mma_gemm<true, true, false, true, true><<<gridD, 256, SMEM>>>(
        th, tl, wh + 65536, wl + 65536, fc0_b + 256, x, xh, xl, N, 256, 256);

    // 3. radial basis
    rbf_kernel<<<(E + 255) / 256, 256>>>(ei, pos, freqs, E);

    // 4. interaction blocks
    for (int n = 0; n < 4; n++) {
        cudaMemsetAsync(agg, 0, (size_t)N * 64 * sizeof(float));

        // v = x @ Wv[n]  (fp32 only)
        mma_gemm<false, false, false, true, false><<<gridM, 256, SMEM>>>(
            xh, xl, wh + 655360 + n * 16384, wl + 655360 + n * 16384, nullptr,
            vbuf, nullptr, nullptr, N, 256, 64);

        // gated messages + vector-red scatter
        edge_msg_kernel<<<(E * 16 + 255) / 256, 256>>>(
            ei, conv_Wrbf + (size_t)n * 12 * 64, E);

        // agg -> hi/lo
        split_agg_kernel<<<(N * 64 + 255) / 256, 256>>>(N * 64);

        // x = x + agg @ Wout[n]  (fp32 + split)
        mma_gemm<false, false, true, true, true><<<gridD, 256, SMEM>>>(
            aggh, aggl, wh + 655360 + 65536 + n * 16384,
            wl + 655360 + 65536 + n * 16384, nullptr, x, xh, xl, N, 64, 256);

        // tmp = gelu(x@W0+b0)  (split only)
        const __nv_bfloat16* W0h = wh + (size_t)(2 + 2 * n) * 65536;
        const __nv_bfloat16* W0l = wl + (size_t)(2 + 2 * n) * 65536;
        const __nv_bfloat16* W1h = wh + (size_t)(3 + 2 * n) * 65536;
        const __nv_bfloat16* W1l = wl + (size_t)(3 + 2 * n) * 65536;
        const float* b0 = fc_b + (size_t)n * 2 * 256;
        const float* b1 = b0 + 256;
        mma_gemm<true, true, false, false, true><<<gridD, 256, SMEM>>>(
            xh, xl, W0h, W0l, b0, nullptr, th, tl, N, 256, 256);
        // x = x + gelu(tmp@W1+b1)  (fp32 + split)
        mma_gemm<true, true, true, true, true><<<gridD, 256, SMEM>>>(
            th, tl, W1h, W1l, b1, x, xh, xl, N, 256, 256);
    }
}